// round 3
// baseline (speedup 1.0000x reference)
#include <cuda_runtime.h>
#include <math.h>

#define Bdim 4
#define Ldim 2048
#define Cdim 1024
#define Hdim 16
#define Ddim 64
#define Mdim (Bdim*Ldim)          // 8192
#define NQKV (3*Cdim)             // 3072
#define MAX_SCALE_MUL 4.605170185988091f   // log(100)

// ---- scratch (allocation-free rule: __device__ globals) ----
__device__ float g_q[Bdim*Hdim*Ldim*Ddim];   // [b,h,l,d]
__device__ float g_k[Bdim*Hdim*Ldim*Ddim];
__device__ float g_v[Bdim*Hdim*Ldim*Ddim];
__device__ float g_ctx[Mdim*Cdim];           // [b,l,c] attention output (pre-proj)

// ============================================================
// Kernel 1: QKV GEMM. out[m,n] = x[m,:].W_qkv[n,:] + bias(n)
// scatter epilogue into g_q/g_k/g_v in [b,h,l,d] layout.
// 64x64 block tile, BK=16, 4x4 per-thread microtile, 256 threads.
// ============================================================
__global__ __launch_bounds__(256) void qkv_gemm_kernel(
    const float* __restrict__ A, const float* __restrict__ W,
    const float* __restrict__ qb, const float* __restrict__ vb)
{
    __shared__ float As[16][68];
    __shared__ float Ws[16][68];
    const int bm = blockIdx.y * 64;
    const int bn = blockIdx.x * 64;
    const int tid = threadIdx.x;
    const int tx = tid & 15, ty = tid >> 4;
    const int lrow = tid >> 2;
    const int lk   = (tid & 3) << 2;

    const float* Arow = A + (size_t)(bm + lrow) * Cdim + lk;
    const float* Wrow = W + (size_t)(bn + lrow) * Cdim + lk;

    float acc[4][4];
#pragma unroll
    for (int i = 0; i < 4; i++)
#pragma unroll
        for (int j = 0; j < 4; j++) acc[i][j] = 0.f;

    for (int k0 = 0; k0 < Cdim; k0 += 16) {
        float4 a = *(const float4*)(Arow + k0);
        float4 w = *(const float4*)(Wrow + k0);
        As[lk+0][lrow]=a.x; As[lk+1][lrow]=a.y; As[lk+2][lrow]=a.z; As[lk+3][lrow]=a.w;
        Ws[lk+0][lrow]=w.x; Ws[lk+1][lrow]=w.y; Ws[lk+2][lrow]=w.z; Ws[lk+3][lrow]=w.w;
        __syncthreads();
#pragma unroll
        for (int kk = 0; kk < 16; kk++) {
            float4 a4 = *(const float4*)&As[kk][ty*4];
            float4 w4 = *(const float4*)&Ws[kk][tx*4];
            float ra[4] = {a4.x, a4.y, a4.z, a4.w};
            float rw[4] = {w4.x, w4.y, w4.z, w4.w};
#pragma unroll
            for (int i = 0; i < 4; i++)
#pragma unroll
                for (int j = 0; j < 4; j++) acc[i][j] += ra[i] * rw[j];
        }
        __syncthreads();
    }

    // Epilogue: a 64-col block lies fully inside one of {q,k,v} and one head.
    const int which = bn >> 10;          // 0:q 1:k 2:v
    const int cbase = bn & 1023;         // h*64
    const int h = cbase >> 6;
    float* dst = (which == 0) ? g_q : ((which == 1) ? g_k : g_v);
    float bj[4];
#pragma unroll
    for (int j = 0; j < 4; j++) {
        int c = cbase + tx*4 + j;
        bj[j] = (which == 0) ? qb[c] : ((which == 2) ? vb[c] : 0.f);
    }
#pragma unroll
    for (int i = 0; i < 4; i++) {
        int m = bm + ty*4 + i;
        int b = m >> 11;                 // m / L
        int l = m & (Ldim - 1);
        float4 o;
        o.x = acc[i][0] + bj[0];
        o.y = acc[i][1] + bj[1];
        o.z = acc[i][2] + bj[2];
        o.w = acc[i][3] + bj[3];
        *(float4*)(dst + (((size_t)((b*Hdim + h)*Ldim + l)) << 6) + tx*4) = o;
    }
}

// ============================================================
// Kernel 2: L2-normalize q and k rows (D=64). One warp per row.
// q gets * exp(min(scale_mul_log[h], log 100)).
// ============================================================
__global__ __launch_bounds__(256) void norm_kernel(const float* __restrict__ sml)
{
    const int NR = Bdim*Hdim*Ldim;
    int w = blockIdx.x * 8 + (threadIdx.x >> 5);
    int lane = threadIdx.x & 31;
    bool is_q = (w < NR);
    float* p = is_q ? g_q : g_k;
    int r = is_q ? w : (w - NR);
    float a0 = p[(size_t)r*64 + lane];
    float a1 = p[(size_t)r*64 + lane + 32];
    float s = a0*a0 + a1*a1;
#pragma unroll
    for (int off = 16; off > 0; off >>= 1)
        s += __shfl_xor_sync(0xffffffffu, s, off);
    float mul = 1.0f;
    if (is_q) {
        int h = (r >> 11) & (Hdim - 1);   // (r/L) % H
        mul = __expf(fminf(sml[h], MAX_SCALE_MUL));
    }
    float inv = mul / fmaxf(sqrtf(s), 1e-12f);
    p[(size_t)r*64 + lane]      = a0 * inv;
    p[(size_t)r*64 + lane + 32] = a1 * inv;
}

__device__ __forceinline__ float hmax16(float v) {
#pragma unroll
    for (int off = 8; off > 0; off >>= 1)
        v = fmaxf(v, __shfl_xor_sync(0xffffffffu, v, off));
    return v;
}
__device__ __forceinline__ float hsum16(float v) {
#pragma unroll
    for (int off = 8; off > 0; off >>= 1)
        v += __shfl_xor_sync(0xffffffffu, v, off);
    return v;
}

// ============================================================
// Kernel 3: flash attention. Block = one (b,h) x 64-query tile.
// Online softmax, scale=1. 48KB static smem exactly:
//   Qs [d][q] (64x64), KP: K as [d][k] then reused as P [k][q], Vs [k][d].
// ============================================================
__global__ __launch_bounds__(256) void attn_kernel()
{
    __shared__ float Qs[64*64];
    __shared__ float KP[64*64];
    __shared__ float Vs[64*64];

    const int bh = blockIdx.y;
    const int q0 = blockIdx.x * 64;
    const float* Qp = g_q + (size_t)bh * Ldim * Ddim;
    const float* Kp = g_k + (size_t)bh * Ldim * Ddim;
    const float* Vp = g_v + (size_t)bh * Ldim * Ddim;

    const int tid = threadIdx.x;
    const int tx = tid & 15, ty = tid >> 4;
    const int r  = tid >> 2;          // 0..63
    const int c0 = (tid & 3) << 4;    // 0,16,32,48

    // load Q tile transposed -> Qs[d][q]
#pragma unroll
    for (int v = 0; v < 4; v++) {
        float4 x = *(const float4*)(Qp + (size_t)(q0 + r)*64 + c0 + v*4);
        Qs[(c0 + v*4 + 0)*64 + r] = x.x;
        Qs[(c0 + v*4 + 1)*64 + r] = x.y;
        Qs[(c0 + v*4 + 2)*64 + r] = x.z;
        Qs[(c0 + v*4 + 3)*64 + r] = x.w;
    }

    float O[4][4];
    float mrow[4], lrow[4];
#pragma unroll
    for (int i = 0; i < 4; i++) {
        mrow[i] = -1e30f; lrow[i] = 0.f;
#pragma unroll
        for (int j = 0; j < 4; j++) O[i][j] = 0.f;
    }

    for (int kt = 0; kt < Ldim/64; kt++) {
        const float* Kt = Kp + (size_t)kt * 64 * 64;
        const float* Vt = Vp + (size_t)kt * 64 * 64;
        __syncthreads();   // prev iteration's P/V reads complete
#pragma unroll
        for (int v = 0; v < 4; v++) {
            float4 x = *(const float4*)(Kt + (size_t)r*64 + c0 + v*4);
            KP[(c0 + v*4 + 0)*64 + r] = x.x;
            KP[(c0 + v*4 + 1)*64 + r] = x.y;
            KP[(c0 + v*4 + 2)*64 + r] = x.z;
            KP[(c0 + v*4 + 3)*64 + r] = x.w;
            float4 y = *(const float4*)(Vt + (size_t)r*64 + c0 + v*4);
            *(float4*)&Vs[r*64 + c0 + v*4] = y;
        }
        __syncthreads();

        // S = Q^T-tile . K-tile : S[q][k], q=ty*4+i, k=tx*4+j
        float S[4][4];
#pragma unroll
        for (int i = 0; i < 4; i++)
#pragma unroll
            for (int j = 0; j < 4; j++) S[i][j] = 0.f;
#pragma unroll 16
        for (int d = 0; d < 64; d++) {
            float4 q4 = *(const float4*)&Qs[d*64 + ty*4];
            float4 k4 = *(const float4*)&KP[d*64 + tx*4];
            float rq[4] = {q4.x, q4.y, q4.z, q4.w};
            float rk[4] = {k4.x, k4.y, k4.z, k4.w};
#pragma unroll
            for (int i = 0; i < 4; i++)
#pragma unroll
                for (int j = 0; j < 4; j++) S[i][j] += rq[i] * rk[j];
        }
        __syncthreads();   // done reading K -> KP reusable as P

        // online softmax per q row (reduce across 16 tx lanes = half-warp)
#pragma unroll
        for (int i = 0; i < 4; i++) {
            float mx = fmaxf(fmaxf(S[i][0], S[i][1]), fmaxf(S[i][2], S[i][3]));
            mx = hmax16(mx);
            float mnew = fmaxf(mrow[i], mx);
            float corr = __expf(mrow[i] - mnew);
            float rs = 0.f;
#pragma unroll
            for (int j = 0; j < 4; j++) {
                S[i][j] = __expf(S[i][j] - mnew);
                rs += S[i][j];
            }
            rs = hsum16(rs);
            mrow[i] = mnew;
            lrow[i] = lrow[i] * corr + rs;
#pragma unroll
            for (int j = 0; j < 4; j++) {
                O[i][j] *= corr;
                KP[(tx*4 + j)*64 + ty*4 + i] = S[i][j];   // P transposed [k][q]
            }
        }
        __syncthreads();

        // O[q][d] += sum_k P[k][q] * V[k][d]
#pragma unroll 8
        for (int k = 0; k < 64; k++) {
            float4 p4 = *(const float4*)&KP[k*64 + ty*4];
            float4 v4 = *(const float4*)&Vs[k*64 + tx*4];
            float rp[4] = {p4.x, p4.y, p4.z, p4.w};
            float rv[4] = {v4.x, v4.y, v4.z, v4.w};
#pragma unroll
            for (int i = 0; i < 4; i++)
#pragma unroll
                for (int j = 0; j < 4; j++) O[i][j] += rp[i] * rv[j];
        }
    }

    // write ctx [b,l,c], c = h*64 + d
    const int b = bh >> 4, h = bh & 15;
#pragma unroll
    for (int i = 0; i < 4; i++) {
        int q = q0 + ty*4 + i;
        float inv = 1.0f / lrow[i];
        float4 o;
        o.x = O[i][0]*inv; o.y = O[i][1]*inv; o.z = O[i][2]*inv; o.w = O[i][3]*inv;
        *(float4*)&g_ctx[((size_t)(b*Ldim + q))*Cdim + h*64 + tx*4] = o;
    }
}

// ============================================================
// Kernel 4: out = ctx @ W_proj^T + b_proj
// ============================================================
__global__ __launch_bounds__(256) void proj_gemm_kernel(
    const float* __restrict__ W, const float* __restrict__ bp,
    float* __restrict__ out)
{
    __shared__ float As[16][68];
    __shared__ float Ws[16][68];
    const int bm = blockIdx.y * 64;
    const int bn = blockIdx.x * 64;
    const int tid = threadIdx.x;
    const int tx = tid & 15, ty = tid >> 4;
    const int lrow = tid >> 2;
    const int lk   = (tid & 3) << 2;

    const float* Arow = g_ctx + (size_t)(bm + lrow) * Cdim + lk;
    const float* Wrow = W + (size_t)(bn + lrow) * Cdim + lk;

    float acc[4][4];
#pragma unroll
    for (int i = 0; i < 4; i++)
#pragma unroll
        for (int j = 0; j < 4; j++) acc[i][j] = 0.f;

    for (int k0 = 0; k0 < Cdim; k0 += 16) {
        float4 a = *(const float4*)(Arow + k0);
        float4 w = *(const float4*)(Wrow + k0);
        As[lk+0][lrow]=a.x; As[lk+1][lrow]=a.y; As[lk+2][lrow]=a.z; As[lk+3][lrow]=a.w;
        Ws[lk+0][lrow]=w.x; Ws[lk+1][lrow]=w.y; Ws[lk+2][lrow]=w.z; Ws[lk+3][lrow]=w.w;
        __syncthreads();
#pragma unroll
        for (int kk = 0; kk < 16; kk++) {
            float4 a4 = *(const float4*)&As[kk][ty*4];
            float4 w4 = *(const float4*)&Ws[kk][tx*4];
            float ra[4] = {a4.x, a4.y, a4.z, a4.w};
            float rw[4] = {w4.x, w4.y, w4.z, w4.w};
#pragma unroll
            for (int i = 0; i < 4; i++)
#pragma unroll
                for (int j = 0; j < 4; j++) acc[i][j] += ra[i] * rw[j];
        }
        __syncthreads();
    }

    float bj[4];
#pragma unroll
    for (int j = 0; j < 4; j++) bj[j] = bp[bn + tx*4 + j];
#pragma unroll
    for (int i = 0; i < 4; i++) {
        int m = bm + ty*4 + i;
        float4 o;
        o.x = acc[i][0] + bj[0];
        o.y = acc[i][1] + bj[1];
        o.z = acc[i][2] + bj[2];
        o.w = acc[i][3] + bj[3];
        *(float4*)(out + (size_t)m*Cdim + bn + tx*4) = o;
    }
}

extern "C" void kernel_launch(void* const* d_in, const int* in_sizes, int n_in,
                              void* d_out, int out_size)
{
    const float* x     = (const float*)d_in[0];
    const float* Wqkv  = (const float*)d_in[1];
    const float* qb    = (const float*)d_in[2];
    const float* vb    = (const float*)d_in[3];
    const float* sml   = (const float*)d_in[4];
    const float* Wproj = (const float*)d_in[5];
    const float* bproj = (const float*)d_in[6];
    float* out = (float*)d_out;

    qkv_gemm_kernel<<<dim3(NQKV/64, Mdim/64), 256>>>(x, Wqkv, qb, vb);
    norm_kernel<<<(2*Bdim*Hdim*Ldim)/8, 256>>>(sml);
    attn_kernel<<<dim3(Ldim/64, Bdim*Hdim), 256>>>();
    proj_gemm_kernel<<<dim3(Cdim/64, Mdim/64), 256>>>(Wproj, bproj, out);
}

// round 4
// speedup vs baseline: 1.0002x; 1.0002x over previous
#include <cuda_runtime.h>
#include <math.h>

#define Bdim 4
#define Ldim 2048
#define Cdim 1024
#define Hdim 16
#define Ddim 64
#define Mdim (Bdim*Ldim)          // 8192
#define NQKV (3*Cdim)             // 3072
#define MAX_SCALE_MUL 4.605170185988091f   // log(100)

// ---- scratch (allocation-free rule: __device__ globals) ----
__device__ float g_q[Bdim*Hdim*Ldim*Ddim];   // [b,h,l,d]
__device__ float g_k[Bdim*Hdim*Ldim*Ddim];
__device__ float g_v[Bdim*Hdim*Ldim*Ddim];
__device__ float g_ctx[Mdim*Cdim];           // [b,l,c] attention output (pre-proj)

// ============================================================
// Kernel 1: QKV GEMM. out[m,n] = x[m,:].W_qkv[n,:] + bias(n)
// scatter epilogue into g_q/g_k/g_v in [b,h,l,d] layout.
// 64x64 block tile, BK=16, 4x4 per-thread microtile, 256 threads.
// ============================================================
__global__ __launch_bounds__(256) void qkv_gemm_kernel(
    const float* __restrict__ A, const float* __restrict__ W,
    const float* __restrict__ qb, const float* __restrict__ vb)
{
    __shared__ float As[16][68];
    __shared__ float Ws[16][68];
    const int bm = blockIdx.y * 64;
    const int bn = blockIdx.x * 64;
    const int tid = threadIdx.x;
    const int tx = tid & 15, ty = tid >> 4;
    const int lrow = tid >> 2;
    const int lk   = (tid & 3) << 2;

    const float* Arow = A + (size_t)(bm + lrow) * Cdim + lk;
    const float* Wrow = W + (size_t)(bn + lrow) * Cdim + lk;

    float acc[4][4];
#pragma unroll
    for (int i = 0; i < 4; i++)
#pragma unroll
        for (int j = 0; j < 4; j++) acc[i][j] = 0.f;

    for (int k0 = 0; k0 < Cdim; k0 += 16) {
        float4 a = *(const float4*)(Arow + k0);
        float4 w = *(const float4*)(Wrow + k0);
        As[lk+0][lrow]=a.x; As[lk+1][lrow]=a.y; As[lk+2][lrow]=a.z; As[lk+3][lrow]=a.w;
        Ws[lk+0][lrow]=w.x; Ws[lk+1][lrow]=w.y; Ws[lk+2][lrow]=w.z; Ws[lk+3][lrow]=w.w;
        __syncthreads();
#pragma unroll
        for (int kk = 0; kk < 16; kk++) {
            float4 a4 = *(const float4*)&As[kk][ty*4];
            float4 w4 = *(const float4*)&Ws[kk][tx*4];
            float ra[4] = {a4.x, a4.y, a4.z, a4.w};
            float rw[4] = {w4.x, w4.y, w4.z, w4.w};
#pragma unroll
            for (int i = 0; i < 4; i++)
#pragma unroll
                for (int j = 0; j < 4; j++) acc[i][j] += ra[i] * rw[j];
        }
        __syncthreads();
    }

    // Epilogue: a 64-col block lies fully inside one of {q,k,v} and one head.
    const int which = bn >> 10;          // 0:q 1:k 2:v
    const int cbase = bn & 1023;         // h*64
    const int h = cbase >> 6;
    float* dst = (which == 0) ? g_q : ((which == 1) ? g_k : g_v);
    float bj[4];
#pragma unroll
    for (int j = 0; j < 4; j++) {
        int c = cbase + tx*4 + j;
        bj[j] = (which == 0) ? qb[c] : ((which == 2) ? vb[c] : 0.f);
    }
#pragma unroll
    for (int i = 0; i < 4; i++) {
        int m = bm + ty*4 + i;
        int b = m >> 11;                 // m / L
        int l = m & (Ldim - 1);
        float4 o;
        o.x = acc[i][0] + bj[0];
        o.y = acc[i][1] + bj[1];
        o.z = acc[i][2] + bj[2];
        o.w = acc[i][3] + bj[3];
        *(float4*)(dst + (((size_t)((b*Hdim + h)*Ldim + l)) << 6) + tx*4) = o;
    }
}

// ============================================================
// Kernel 2: L2-normalize q and k rows (D=64). One warp per row.
// q gets * exp(min(scale_mul_log[h], log 100)).
// ============================================================
__global__ __launch_bounds__(256) void norm_kernel(const float* __restrict__ sml)
{
    const int NR = Bdim*Hdim*Ldim;
    int w = blockIdx.x * 8 + (threadIdx.x >> 5);
    int lane = threadIdx.x & 31;
    bool is_q = (w < NR);
    float* p = is_q ? g_q : g_k;
    int r = is_q ? w : (w - NR);
    float a0 = p[(size_t)r*64 + lane];
    float a1 = p[(size_t)r*64 + lane + 32];
    float s = a0*a0 + a1*a1;
#pragma unroll
    for (int off = 16; off > 0; off >>= 1)
        s += __shfl_xor_sync(0xffffffffu, s, off);
    float mul = 1.0f;
    if (is_q) {
        int h = (r >> 11) & (Hdim - 1);   // (r/L) % H
        mul = __expf(fminf(sml[h], MAX_SCALE_MUL));
    }
    float inv = mul / fmaxf(sqrtf(s), 1e-12f);
    p[(size_t)r*64 + lane]      = a0 * inv;
    p[(size_t)r*64 + lane + 32] = a1 * inv;
}

__device__ __forceinline__ float hmax16(float v) {
#pragma unroll
    for (int off = 8; off > 0; off >>= 1)
        v = fmaxf(v, __shfl_xor_sync(0xffffffffu, v, off));
    return v;
}
__device__ __forceinline__ float hsum16(float v) {
#pragma unroll
    for (int off = 8; off > 0; off >>= 1)
        v += __shfl_xor_sync(0xffffffffu, v, off);
    return v;
}

// ============================================================
// Kernel 3: flash attention. Block = one (b,h) x 64-query tile.
// Online softmax, scale=1. 48KB static smem exactly:
//   Qs [d][q] (64x64), KP: K as [d][k] then reused as P [k][q], Vs [k][d].
// ============================================================
__global__ __launch_bounds__(256) void attn_kernel()
{
    __shared__ float Qs[64*64];
    __shared__ float KP[64*64];
    __shared__ float Vs[64*64];

    const int bh = blockIdx.y;
    const int q0 = blockIdx.x * 64;
    const float* Qp = g_q + (size_t)bh * Ldim * Ddim;
    const float* Kp = g_k + (size_t)bh * Ldim * Ddim;
    const float* Vp = g_v + (size_t)bh * Ldim * Ddim;

    const int tid = threadIdx.x;
    const int tx = tid & 15, ty = tid >> 4;
    const int r  = tid >> 2;          // 0..63
    const int c0 = (tid & 3) << 4;    // 0,16,32,48

    // load Q tile transposed -> Qs[d][q]
#pragma unroll
    for (int v = 0; v < 4; v++) {
        float4 x = *(const float4*)(Qp + (size_t)(q0 + r)*64 + c0 + v*4);
        Qs[(c0 + v*4 + 0)*64 + r] = x.x;
        Qs[(c0 + v*4 + 1)*64 + r] = x.y;
        Qs[(c0 + v*4 + 2)*64 + r] = x.z;
        Qs[(c0 + v*4 + 3)*64 + r] = x.w;
    }

    float O[4][4];
    float mrow[4], lrow[4];
#pragma unroll
    for (int i = 0; i < 4; i++) {
        mrow[i] = -1e30f; lrow[i] = 0.f;
#pragma unroll
        for (int j = 0; j < 4; j++) O[i][j] = 0.f;
    }

    for (int kt = 0; kt < Ldim/64; kt++) {
        const float* Kt = Kp + (size_t)kt * 64 * 64;
        const float* Vt = Vp + (size_t)kt * 64 * 64;
        __syncthreads();   // prev iteration's P/V reads complete
#pragma unroll
        for (int v = 0; v < 4; v++) {
            float4 x = *(const float4*)(Kt + (size_t)r*64 + c0 + v*4);
            KP[(c0 + v*4 + 0)*64 + r] = x.x;
            KP[(c0 + v*4 + 1)*64 + r] = x.y;
            KP[(c0 + v*4 + 2)*64 + r] = x.z;
            KP[(c0 + v*4 + 3)*64 + r] = x.w;
            float4 y = *(const float4*)(Vt + (size_t)r*64 + c0 + v*4);
            *(float4*)&Vs[r*64 + c0 + v*4] = y;
        }
        __syncthreads();

        // S = Q^T-tile . K-tile : S[q][k], q=ty*4+i, k=tx*4+j
        float S[4][4];
#pragma unroll
        for (int i = 0; i < 4; i++)
#pragma unroll
            for (int j = 0; j < 4; j++) S[i][j] = 0.f;
#pragma unroll 16
        for (int d = 0; d < 64; d++) {
            float4 q4 = *(const float4*)&Qs[d*64 + ty*4];
            float4 k4 = *(const float4*)&KP[d*64 + tx*4];
            float rq[4] = {q4.x, q4.y, q4.z, q4.w};
            float rk[4] = {k4.x, k4.y, k4.z, k4.w};
#pragma unroll
            for (int i = 0; i < 4; i++)
#pragma unroll
                for (int j = 0; j < 4; j++) S[i][j] += rq[i] * rk[j];
        }
        __syncthreads();   // done reading K -> KP reusable as P

        // online softmax per q row (reduce across 16 tx lanes = half-warp)
#pragma unroll
        for (int i = 0; i < 4; i++) {
            float mx = fmaxf(fmaxf(S[i][0], S[i][1]), fmaxf(S[i][2], S[i][3]));
            mx = hmax16(mx);
            float mnew = fmaxf(mrow[i], mx);
            float corr = __expf(mrow[i] - mnew);
            float rs = 0.f;
#pragma unroll
            for (int j = 0; j < 4; j++) {
                S[i][j] = __expf(S[i][j] - mnew);
                rs += S[i][j];
            }
            rs = hsum16(rs);
            mrow[i] = mnew;
            lrow[i] = lrow[i] * corr + rs;
#pragma unroll
            for (int j = 0; j < 4; j++) {
                O[i][j] *= corr;
                KP[(tx*4 + j)*64 + ty*4 + i] = S[i][j];   // P transposed [k][q]
            }
        }
        __syncthreads();

        // O[q][d] += sum_k P[k][q] * V[k][d]
#pragma unroll 8
        for (int k = 0; k < 64; k++) {
            float4 p4 = *(const float4*)&KP[k*64 + ty*4];
            float4 v4 = *(const float4*)&Vs[k*64 + tx*4];
            float rp[4] = {p4.x, p4.y, p4.z, p4.w};
            float rv[4] = {v4.x, v4.y, v4.z, v4.w};
#pragma unroll
            for (int i = 0; i < 4; i++)
#pragma unroll
                for (int j = 0; j < 4; j++) O[i][j] += rp[i] * rv[j];
        }
    }

    // write ctx [b,l,c], c = h*64 + d
    const int b = bh >> 4, h = bh & 15;
#pragma unroll
    for (int i = 0; i < 4; i++) {
        int q = q0 + ty*4 + i;
        float inv = 1.0f / lrow[i];
        float4 o;
        o.x = O[i][0]*inv; o.y = O[i][1]*inv; o.z = O[i][2]*inv; o.w = O[i][3]*inv;
        *(float4*)&g_ctx[((size_t)(b*Ldim + q))*Cdim + h*64 + tx*4] = o;
    }
}

// ============================================================
// Kernel 4: out = ctx @ W_proj^T + b_proj
// ============================================================
__global__ __launch_bounds__(256) void proj_gemm_kernel(
    const float* __restrict__ W, const float* __restrict__ bp,
    float* __restrict__ out)
{
    __shared__ float As[16][68];
    __shared__ float Ws[16][68];
    const int bm = blockIdx.y * 64;
    const int bn = blockIdx.x * 64;
    const int tid = threadIdx.x;
    const int tx = tid & 15, ty = tid >> 4;
    const int lrow = tid >> 2;
    const int lk   = (tid & 3) << 2;

    const float* Arow = g_ctx + (size_t)(bm + lrow) * Cdim + lk;
    const float* Wrow = W + (size_t)(bn + lrow) * Cdim + lk;

    float acc[4][4];
#pragma unroll
    for (int i = 0; i < 4; i++)
#pragma unroll
        for (int j = 0; j < 4; j++) acc[i][j] = 0.f;

    for (int k0 = 0; k0 < Cdim; k0 += 16) {
        float4 a = *(const float4*)(Arow + k0);
        float4 w = *(const float4*)(Wrow + k0);
        As[lk+0][lrow]=a.x; As[lk+1][lrow]=a.y; As[lk+2][lrow]=a.z; As[lk+3][lrow]=a.w;
        Ws[lk+0][lrow]=w.x; Ws[lk+1][lrow]=w.y; Ws[lk+2][lrow]=w.z; Ws[lk+3][lrow]=w.w;
        __syncthreads();
#pragma unroll
        for (int kk = 0; kk < 16; kk++) {
            float4 a4 = *(const float4*)&As[kk][ty*4];
            float4 w4 = *(const float4*)&Ws[kk][tx*4];
            float ra[4] = {a4.x, a4.y, a4.z, a4.w};
            float rw[4] = {w4.x, w4.y, w4.z, w4.w};
#pragma unroll
            for (int i = 0; i < 4; i++)
#pragma unroll
                for (int j = 0; j < 4; j++) acc[i][j] += ra[i] * rw[j];
        }
        __syncthreads();
    }

    float bj[4];
#pragma unroll
    for (int j = 0; j < 4; j++) bj[j] = bp[bn + tx*4 + j];
#pragma unroll
    for (int i = 0; i < 4; i++) {
        int m = bm + ty*4 + i;
        float4 o;
        o.x = acc[i][0] + bj[0];
        o.y = acc[i][1] + bj[1];
        o.z = acc[i][2] + bj[2];
        o.w = acc[i][3] + bj[3];
        *(float4*)(out + (size_t)m*Cdim + bn + tx*4) = o;
    }
}

extern "C" void kernel_launch(void* const* d_in, const int* in_sizes, int n_in,
                              void* d_out, int out_size)
{
    const float* x     = (const float*)d_in[0];
    const float* Wqkv  = (const float*)d_in[1];
    const float* qb    = (const float*)d_in[2];
    const float* vb    = (const float*)d_in[3];
    const float* sml   = (const float*)d_in[4];
    const float* Wproj = (const float*)d_in[5];
    const float* bproj = (const float*)d_in[6];
    float* out = (float*)d_out;

    qkv_gemm_kernel<<<dim3(NQKV/64, Mdim/64), 256>>>(x, Wqkv, qb, vb);
    norm_kernel<<<(2*Bdim*Hdim*Ldim)/8, 256>>>(sml);
    attn_kernel<<<dim3(Ldim/64, Bdim*Hdim), 256>>>();
    proj_gemm_kernel<<<dim3(Cdim/64, Mdim/64), 256>>>(Wproj, bproj, out);
}

// round 6
// speedup vs baseline: 3.3363x; 3.3356x over previous
#include <cuda_runtime.h>
#include <cuda_bf16.h>
#include <math.h>

#define Bdim 4
#define Ldim 2048
#define Cdim 1024
#define Hdim 16
#define Mdim (Bdim*Ldim)          // 8192
#define MAX_SCALE_MUL 4.605170185988091f   // log(100)

// ---- scratch (__device__ globals; allocation-free rule) ----
__device__ float g_q  [Bdim*Hdim*Ldim*64];   // [b,h,l,d]
__device__ float g_k  [Bdim*Hdim*Ldim*64];   // [b,h,l,d]
__device__ float g_vt [Bdim*Hdim*64*Ldim];   // [b,h,d,l]  (V pre-transposed)
__device__ float g_ctx[Mdim*Cdim];           // [b,l,c]

// ============================================================
// bf16 hi/lo split (packed pairs) + m16n8k16 bf16 mma
// ============================================================
__device__ __forceinline__ void split2(float x0, float x1, unsigned &hi, unsigned &lo) {
    __nv_bfloat162 h2 = __floats2bfloat162_rn(x0, x1);
    float hx = __bfloat162float(h2.x), hy = __bfloat162float(h2.y);
    __nv_bfloat162 l2 = __floats2bfloat162_rn(x0 - hx, x1 - hy);
    hi = *reinterpret_cast<unsigned*>(&h2);
    lo = *reinterpret_cast<unsigned*>(&l2);
}

__device__ __forceinline__ void mma16816(float* c, const unsigned* a, const unsigned* b) {
    asm volatile(
        "mma.sync.aligned.m16n8k16.row.col.f32.bf16.bf16.f32 "
        "{%0,%1,%2,%3},{%4,%5,%6,%7},{%8,%9},{%0,%1,%2,%3};\n"
        : "+f"(c[0]), "+f"(c[1]), "+f"(c[2]), "+f"(c[3])
        : "r"(a[0]), "r"(a[1]), "r"(a[2]), "r"(a[3]), "r"(b[0]), "r"(b[1]));
}
// acc += ah*bl + al*bh + ah*bh   (drops lo*lo)
__device__ __forceinline__ void mma3(float* c, const unsigned* ah, const unsigned* al,
                                     const unsigned* bh, const unsigned* bl) {
    mma16816(c, ah, bl);
    mma16816(c, al, bh);
    mma16816(c, ah, bh);
}

// ============================================================
// smem tile loader: 128 rows x 64 fp32 cols -> hi/lo bf16x2 u32[128][32]
// physical col = logical_col ^ (4*(row&7))  (conflict-free swizzle)
// ============================================================
__device__ __forceinline__ void load_tile_128x64(
    const float* __restrict__ src, size_t row0, int ldg, int k0,
    unsigned* __restrict__ Hi, unsigned* __restrict__ Lo, int tid)
{
#pragma unroll
    for (int p = 0; p < 8; p++) {
        int r = p*16 + (tid >> 4);
        int j = tid & 15;
        const float4 v = *(const float4*)(src + (row0 + r)*(size_t)ldg + k0 + j*4);
        unsigned h0,l0,h1,l1;
        split2(v.x, v.y, h0, l0);
        split2(v.z, v.w, h1, l1);
        int c = (2*j) ^ ((r & 7) << 2);
        *(uint2*)&Hi[r*32 + c] = make_uint2(h0, h1);
        *(uint2*)&Lo[r*32 + c] = make_uint2(l0, l1);
    }
}

// Vt tile: 64 rows (d) x 128 fp32 (keys) -> u32[64][64]
__device__ __forceinline__ void load_vt_tile(
    const float* __restrict__ Vg, int l0,
    unsigned* __restrict__ Hi, unsigned* __restrict__ Lo, int tid)
{
#pragma unroll
    for (int p = 0; p < 8; p++) {
        int r = p*8 + (tid >> 5);
        int j = tid & 31;
        const float4 v = *(const float4*)(Vg + (size_t)r*Ldim + l0 + j*4);
        unsigned h0,l0_,h1,l1;
        split2(v.x, v.y, h0, l0_);
        split2(v.z, v.w, h1, l1);
        int c = (2*j) ^ ((r & 7) << 2);
        *(uint2*)&Hi[r*64 + c] = make_uint2(h0, h1);
        *(uint2*)&Lo[r*64 + c] = make_uint2(l0_, l1);
    }
}

// ============================================================
// GEMM: C[M,N] = A[M,1024] . W[N,1024]^T  (+bias epilogues)
// MODE 0: QKV (scatter to g_q/g_k/g_vt), MODE 1: proj -> out
// block 128x128, BK=64, 8 warps (2x4), warp tile 64x32
// ============================================================
template<int MODE>
__global__ __launch_bounds__(256) void gemm_ker(
    const float* __restrict__ A, const float* __restrict__ W,
    const float* __restrict__ bq, const float* __restrict__ bv,
    float* __restrict__ out)
{
    extern __shared__ unsigned smg[];
    unsigned *Ahi = smg, *Alo = smg + 4096, *Whi = smg + 8192, *Wlo = smg + 12288;
    const int tid  = threadIdx.x;
    const int lane = tid & 31;
    const int wid  = tid >> 5;
    const int wm   = wid >> 2, wn = wid & 3;
    const int qr   = lane >> 2, qc = lane & 3;
    const int bm = blockIdx.y * 128, bn = blockIdx.x * 128;

    const float* Asrc = (MODE == 1) ? (const float*)g_ctx : A;

    float acc[4][4][4];
#pragma unroll
    for (int i = 0; i < 4; i++)
#pragma unroll
        for (int j = 0; j < 4; j++)
#pragma unroll
            for (int t = 0; t < 4; t++) acc[i][j][t] = 0.f;

    for (int k0 = 0; k0 < Cdim; k0 += 64) {
        __syncthreads();
        load_tile_128x64(Asrc, bm, Cdim, k0, Ahi, Alo, tid);
        load_tile_128x64(W,    bn, Cdim, k0, Whi, Wlo, tid);
        __syncthreads();
#pragma unroll
        for (int ks = 0; ks < 4; ks++) {
            const int c0 = ks*8 + qc, c1 = c0 + 4, sw = qr << 2;
            unsigned ah[4][4], al[4][4], bh[4][2], bl[4][2];
#pragma unroll
            for (int mt = 0; mt < 4; mt++) {
                int r0 = wm*64 + mt*16 + qr, r1 = r0 + 8;
                int i0 = r0*32 + (c0^sw), i1 = r1*32 + (c0^sw);
                int i2 = r0*32 + (c1^sw), i3 = r1*32 + (c1^sw);
                ah[mt][0]=Ahi[i0]; ah[mt][1]=Ahi[i1]; ah[mt][2]=Ahi[i2]; ah[mt][3]=Ahi[i3];
                al[mt][0]=Alo[i0]; al[mt][1]=Alo[i1]; al[mt][2]=Alo[i2]; al[mt][3]=Alo[i3];
            }
#pragma unroll
            for (int nt = 0; nt < 4; nt++) {
                int n0 = wn*32 + nt*8 + qr;
                bh[nt][0]=Whi[n0*32 + (c0^sw)]; bh[nt][1]=Whi[n0*32 + (c1^sw)];
                bl[nt][0]=Wlo[n0*32 + (c0^sw)]; bl[nt][1]=Wlo[n0*32 + (c1^sw)];
            }
#pragma unroll
            for (int mt = 0; mt < 4; mt++)
#pragma unroll
                for (int nt = 0; nt < 4; nt++)
                    mma3(acc[mt][nt], ah[mt], al[mt], bh[nt], bl[nt]);
        }
    }

    if (MODE == 1) {
#pragma unroll
        for (int mt = 0; mt < 4; mt++)
#pragma unroll
            for (int nt = 0; nt < 4; nt++) {
                int m = bm + wm*64 + mt*16 + qr;
                int n = bn + wn*32 + nt*8 + qc*2;
                float b0 = bq[n], b1 = bq[n+1];
                float2 o0 = make_float2(acc[mt][nt][0] + b0, acc[mt][nt][1] + b1);
                float2 o1 = make_float2(acc[mt][nt][2] + b0, acc[mt][nt][3] + b1);
                *(float2*)(out + (size_t)m*Cdim + n)     = o0;
                *(float2*)(out + (size_t)(m+8)*Cdim + n) = o1;
            }
    } else {
        const int which = bn >> 10;        // 0:q 1:k 2:v
        const int cb = bn & 1023;
#pragma unroll
        for (int mt = 0; mt < 4; mt++)
#pragma unroll
            for (int nt = 0; nt < 4; nt++) {
                int nloc = wn*32 + nt*8 + qc*2;
                int ncol = cb + nloc;
                int h = ncol >> 6, d = ncol & 63;
                float b0 = 0.f, b1 = 0.f;
                if (which == 0) { b0 = bq[ncol]; b1 = bq[ncol+1]; }
                if (which == 2) { b0 = bv[ncol]; b1 = bv[ncol+1]; }
#pragma unroll
                for (int hh = 0; hh < 2; hh++) {
                    int m = bm + wm*64 + mt*16 + qr + hh*8;
                    int b = m >> 11, l = m & (Ldim-1);
                    float v0 = acc[mt][nt][hh*2]   + b0;
                    float v1 = acc[mt][nt][hh*2+1] + b1;
                    if (which == 2) {
                        size_t base = ((size_t)(b*Hdim + h)*64 + d)*Ldim + l;
                        g_vt[base]        = v0;
                        g_vt[base + Ldim] = v1;
                    } else {
                        float* dst = (which == 0) ? g_q : g_k;
                        *(float2*)(dst + ((size_t)(b*Hdim + h)*Ldim + l)*64 + d)
                            = make_float2(v0, v1);
                    }
                }
            }
    }
}

// ============================================================
// L2-normalize q,k rows; q gets exp(min(sml[h], log100))
// ============================================================
__global__ __launch_bounds__(256) void norm_kernel(const float* __restrict__ sml)
{
    const int NR = Bdim*Hdim*Ldim;
    int w = blockIdx.x * 8 + (threadIdx.x >> 5);
    int lane = threadIdx.x & 31;
    bool is_q = (w < NR);
    float* p = is_q ? g_q : g_k;
    int r = is_q ? w : (w - NR);
    float a0 = p[(size_t)r*64 + lane];
    float a1 = p[(size_t)r*64 + lane + 32];
    float s = a0*a0 + a1*a1;
#pragma unroll
    for (int off = 16; off > 0; off >>= 1)
        s += __shfl_xor_sync(0xffffffffu, s, off);
    float mul = 1.0f;
    if (is_q) {
        int h = (r >> 11) & (Hdim - 1);
        mul = __expf(fminf(sml[h], MAX_SCALE_MUL));
    }
    float inv = mul / fmaxf(sqrtf(s), 1e-12f);
    p[(size_t)r*64 + lane]      = a0 * inv;
    p[(size_t)r*64 + lane + 32] = a1 * inv;
}

// ============================================================
// Flash attention, tensor cores. Block = (b,h) x 128-query tile.
// 8 warps; warp owns 16 q rows x all 128 keys -> softmax is
// quad-shuffle only. P repacked from S regs for PV (no smem).
// ============================================================
__global__ __launch_bounds__(256) void attn_ker()
{
    extern __shared__ unsigned sma[];
    unsigned *Qhi = sma,         *Qlo = sma + 4096;
    unsigned *Khi = sma + 8192,  *Klo = sma + 12288;
    unsigned *Vhi = sma + 16384, *Vlo = sma + 20480;

    const int tid = threadIdx.x, lane = tid & 31, wid = tid >> 5;
    const int qr = lane >> 2, qc = lane & 3;
    const int bh = blockIdx.y, q0 = blockIdx.x * 128;
    const float* Qg = g_q  + (size_t)bh * Ldim * 64;
    const float* Kg = g_k  + (size_t)bh * Ldim * 64;
    const float* Vg = g_vt + (size_t)bh * 64 * Ldim;

    load_tile_128x64(Qg, q0, 64, 0, Qhi, Qlo, tid);

    float oacc[8][4];
#pragma unroll
    for (int i = 0; i < 8; i++)
#pragma unroll
        for (int t = 0; t < 4; t++) oacc[i][t] = 0.f;
    float mrow[2] = {-1e30f, -1e30f}, lrow[2] = {0.f, 0.f};

    for (int kt = 0; kt < Ldim/128; kt++) {
        __syncthreads();
        load_tile_128x64(Kg, kt*128, 64, 0, Khi, Klo, tid);
        load_vt_tile(Vg, kt*128, Vhi, Vlo, tid);
        __syncthreads();

        // ---- S = Q . K^T  (16 rows x 128 keys per warp) ----
        float sacc[16][4];
#pragma unroll
        for (int i = 0; i < 16; i++)
#pragma unroll
            for (int t = 0; t < 4; t++) sacc[i][t] = 0.f;
#pragma unroll
        for (int ks = 0; ks < 4; ks++) {
            const int c0 = ks*8 + qc, c1 = c0 + 4, sw = qr << 2;
            int r0 = wid*16 + qr, r1 = r0 + 8;
            int i0 = r0*32 + (c0^sw), i1 = r1*32 + (c0^sw);
            int i2 = r0*32 + (c1^sw), i3 = r1*32 + (c1^sw);
            unsigned ah[4] = {Qhi[i0], Qhi[i1], Qhi[i2], Qhi[i3]};
            unsigned al[4] = {Qlo[i0], Qlo[i1], Qlo[i2], Qlo[i3]};
#pragma unroll
            for (int nt = 0; nt < 16; nt++) {
                int n0 = nt*8 + qr;
                unsigned bh2[2] = {Khi[n0*32 + (c0^sw)], Khi[n0*32 + (c1^sw)]};
                unsigned bl2[2] = {Klo[n0*32 + (c0^sw)], Klo[n0*32 + (c1^sw)]};
                mma3(sacc[nt], ah, al, bh2, bl2);
            }
        }

        // ---- online softmax (per row-half; quad reduce) ----
#pragma unroll
        for (int hh = 0; hh < 2; hh++) {
            float mx = -1e30f;
#pragma unroll
            for (int nt = 0; nt < 16; nt++)
                mx = fmaxf(mx, fmaxf(sacc[nt][hh*2], sacc[nt][hh*2+1]));
            mx = fmaxf(mx, __shfl_xor_sync(0xffffffffu, mx, 1));
            mx = fmaxf(mx, __shfl_xor_sync(0xffffffffu, mx, 2));
            float mnew = fmaxf(mrow[hh], mx);
            float corr = __expf(mrow[hh] - mnew);
            float rs = 0.f;
#pragma unroll
            for (int nt = 0; nt < 16; nt++) {
                float e0 = __expf(sacc[nt][hh*2]   - mnew);
                float e1 = __expf(sacc[nt][hh*2+1] - mnew);
                sacc[nt][hh*2] = e0; sacc[nt][hh*2+1] = e1;
                rs += e0 + e1;
            }
            rs += __shfl_xor_sync(0xffffffffu, rs, 1);
            rs += __shfl_xor_sync(0xffffffffu, rs, 2);
            mrow[hh] = mnew;
            lrow[hh] = lrow[hh]*corr + rs;
#pragma unroll
            for (int nt = 0; nt < 8; nt++) {
                oacc[nt][hh*2]   *= corr;
                oacc[nt][hh*2+1] *= corr;
            }
        }

        // ---- O += P . V  (P packed from sacc; Vt smem as B) ----
#pragma unroll
        for (int ks = 0; ks < 8; ks++) {
            unsigned ah[4], al[4];
            split2(sacc[2*ks][0],   sacc[2*ks][1],   ah[0], al[0]);
            split2(sacc[2*ks][2],   sacc[2*ks][3],   ah[1], al[1]);
            split2(sacc[2*ks+1][0], sacc[2*ks+1][1], ah[2], al[2]);
            split2(sacc[2*ks+1][2], sacc[2*ks+1][3], ah[3], al[3]);
            const int c0 = ks*8 + qc, c1 = c0 + 4, sw = qr << 2;
#pragma unroll
            for (int nt = 0; nt < 8; nt++) {
                int n0 = nt*8 + qr;
                unsigned bh2[2] = {Vhi[n0*64 + (c0^sw)], Vhi[n0*64 + (c1^sw)]};
                unsigned bl2[2] = {Vlo[n0*64 + (c0^sw)], Vlo[n0*64 + (c1^sw)]};
                mma3(oacc[nt], ah, al, bh2, bl2);
            }
        }
    }

    // ---- epilogue: normalize rows, write ctx [b,l,c] ----
    const int b = bh >> 4, h = bh & 15;
    const float inv0 = 1.0f / lrow[0], inv1 = 1.0f / lrow[1];
    int q = q0 + wid*16 + qr;
#pragma unroll
    for (int nt = 0; nt < 8; nt++) {
        int d = h*64 + nt*8 + qc*2;
        *(float2*)&g_ctx[(size_t)(b*Ldim + q)*Cdim + d]
            = make_float2(oacc[nt][0]*inv0, oacc[nt][1]*inv0);
        *(float2*)&g_ctx[(size_t)(b*Ldim + q + 8)*Cdim + d]
            = make_float2(oacc[nt][2]*inv1, oacc[nt][3]*inv1);
    }
}

// ============================================================
extern "C" void kernel_launch(void* const* d_in, const int* in_sizes, int n_in,
                              void* d_out, int out_size)
{
    const float* x     = (const float*)d_in[0];
    const float* Wqkv  = (const float*)d_in[1];
    const float* qb    = (const float*)d_in[2];
    const float* vb    = (const float*)d_in[3];
    const float* sml   = (const float*)d_in[4];
    const float* Wproj = (const float*)d_in[5];
    const float* bproj = (const float*)d_in[6];
    float* out = (float*)d_out;

    const int GEMM_SMEM = 16384 * 4;   // 64 KB
    const int ATTN_SMEM = 24576 * 4;   // 96 KB
    cudaFuncSetAttribute(gemm_ker<0>, cudaFuncAttributeMaxDynamicSharedMemorySize, GEMM_SMEM);
    cudaFuncSetAttribute(gemm_ker<1>, cudaFuncAttributeMaxDynamicSharedMemorySize, GEMM_SMEM);
    cudaFuncSetAttribute(attn_ker,    cudaFuncAttributeMaxDynamicSharedMemorySize, ATTN_SMEM);

    gemm_ker<0><<<dim3(3*Cdim/128, Mdim/128), 256, GEMM_SMEM>>>(x, Wqkv, qb, vb, nullptr);
    norm_kernel<<<(2*Bdim*Hdim*Ldim)/8, 256>>>(sml);
    attn_ker<<<dim3(Ldim/128, Bdim*Hdim), 256, ATTN_SMEM>>>();
    gemm_ker<1><<<dim3(Cdim/128, Mdim/128), 256, GEMM_SMEM>>>(nullptr, Wproj, bproj, nullptr, out);
}